// round 17
// baseline (speedup 1.0000x reference)
#include <cuda_runtime.h>
#include <math.h>
#include <limits.h>

// L2loss over bucketized histograms — analytic segment version (R17).
// Sum_p (h1-h2)^2 = sum over segments [x, next(x)) of len*d^2, candidates =
// the 6*256 cum values, deduped at first occurrence.
// R17: SINGLE BLOCK, classic launch, 1024 threads. Thread t evaluates
// candidate t and (if t < 512) candidate t+1024, both interleaved for ILP.
// No cross-block communication of any kind: no atomics, no cluster, no
// device globals. Tail = two-level REDUX block reduce + one STG.

namespace {
constexpr int KBINS = 256;
constexpr int NPIX  = 224 * 224;     // 50176
constexpr int TPB   = 1024;          // 32 warps
constexpr int NENT  = 6 * KBINS;     // 1536 candidate breakpoints
constexpr int NWARP = TPB / 32;      // 32
constexpr int NSPILL = NENT - TPB;   // 512 threads take a second candidate
}

__global__ void __launch_bounds__(TPB)
l2hist_kernel(const float* __restrict__ target,
              const float* __restrict__ output,
              float* __restrict__ out)
{
    __shared__ alignas(16) int s_cum[6][KBINS];
    __shared__ unsigned int    s_wred[NWARP][3];

    const int tid  = threadIdx.x;
    const int lane = tid & 31;
    const int warp = tid >> 5;

    // ---- Scan: warps 0..5 compute floor(cumsum) of their array. ----
    // Lane l owns elements [8l, 8l+8): serial in-lane prefix, Kogge-Stone
    // over lane totals, exclusive offset via shfl_up(1).
    if (warp < 6) {
        const float* src = (warp < 3) ? target + (warp << 8)
                                      : output + ((warp - 3) << 8);
        const float4 v0 = __ldg((const float4*)(src + (lane << 3)));
        const float4 v1 = __ldg((const float4*)(src + (lane << 3) + 4));

        float q0 = v0.x;
        float q1 = q0 + v0.y;
        float q2 = q1 + v0.z;
        float q3 = q2 + v0.w;
        float q4 = q3 + v1.x;
        float q5 = q4 + v1.y;
        float q6 = q5 + v1.z;
        float q7 = q6 + v1.w;          // lane total

        float inc = q7;
        #pragma unroll
        for (int off = 1; off < 32; off <<= 1) {
            const float n = __shfl_up_sync(0xFFFFFFFFu, inc, off);
            if (lane >= off) inc += n;
        }
        float excl = __shfl_up_sync(0xFFFFFFFFu, inc, 1);
        if (lane == 0) excl = 0.0f;

        int4 w0, w1;
        w0.x = __float2int_rd(excl + q0);
        w0.y = __float2int_rd(excl + q1);
        w0.z = __float2int_rd(excl + q2);
        w0.w = __float2int_rd(excl + q3);
        w1.x = __float2int_rd(excl + q4);
        w1.y = __float2int_rd(excl + q5);
        w1.z = __float2int_rd(excl + q6);
        w1.w = __float2int_rd(excl + q7);
        *(int4*)&s_cum[warp][(lane << 3)]     = w0;
        *(int4*)&s_cum[warp][(lane << 3) + 4] = w1;
    }
    __syncthreads();

    // ---- Two candidates per thread (second only for tid < NSPILL),
    //      fully interleaved for memory-level parallelism. ----
    const bool has2 = (tid < NSPILL);
    const int  e0 = tid;
    const int  e1 = has2 ? (tid + TPB) : tid;      // dummy alias when absent

    const int a0 = e0 >> 8, j0 = e0 & (KBINS - 1);
    const int a1 = e1 >> 8, j1 = e1 & (KBINS - 1);
    const int x0 = s_cum[a0][j0];
    const int x1 = s_cum[a1][j1];

    // Saturating searches for both candidates over all 6 arrays (12 chains).
    int s0[6], s1[6];
    #pragma unroll
    for (int a = 0; a < 6; ++a) { s0[a] = 0; s1[a] = 0; }
    #pragma unroll
    for (int w = 128; w; w >>= 1) {
        #pragma unroll
        for (int a = 0; a < 6; ++a) {
            if (s_cum[a][s0[a] + w - 1] <= x0) s0[a] += w;
            if (s_cum[a][s1[a] + w - 1] <= x1) s1[a] += w;
        }
    }

    // Per-candidate: exact counts, presence, next breakpoint, h, len*d^2.
    unsigned int acc[3] = {0u, 0u, 0u};
    #pragma unroll
    for (int k = 0; k < 2; ++k) {
        if (k == 1 && !has2) break;
        const int x     = (k == 0) ? x0 : x1;
        const int a_src = (k == 0) ? a0 : a1;
        const int j_src = (k == 0) ? j0 : j1;
        int* sk = (k == 0) ? s0 : s1;

        int  cnt[6];
        bool pres[6];
        int  nxt = NPIX;
        #pragma unroll
        for (int a = 0; a < 6; ++a) {
            int c = sk[a];
            if (c == KBINS - 1 && s_cum[a][KBINS - 1] <= x) c = KBINS; // 256
            cnt[a]  = c;
            pres[a] = (c > 0) && (s_cum[a][c - 1] == x);
            const int nv = (c < KBINS) ? s_cum[a][c] : INT_MAX;
            nxt = (nv < nxt) ? nv : nxt;
        }
        const int len = (nxt > x) ? (nxt - x) : 0;   // nxt already <= NPIX

        // Dedup: first occurrence of value x (array order, then index).
        bool canonical = (j_src == 0) || (s_cum[a_src][j_src - 1] < x);
        #pragma unroll
        for (int a = 0; a < 6; ++a)
            if (a < a_src && pres[a]) canonical = false;

        if (canonical && len > 0) {
            int h1 = 0, h2 = 0;
            #pragma unroll
            for (int c = 0; c < 3; ++c) {
                const int c1 = cnt[c], c2 = cnt[c + 3];
                if (c1 <= KBINS - 2)   h1 = c1;
                else if (c1 == KBINS)  h1 = KBINS - 1;   // count was 256
                /* c1 == 255: keep previous channel's value */
                if (c2 <= KBINS - 2)   h2 = c2;
                else if (c2 == KBINS)  h2 = KBINS - 1;
                const int d = h1 - h2;
                // len*d^2 <= 50176*65025 < 2^32; channel totals are sums
                // over disjoint segments tiling [0, NPIX): fit u32.
                acc[c] += (unsigned int)len * (unsigned int)(d * d);
            }
        }
    }

    // ---- Two-level block reduce (REDUX), then single STG. ----
    #pragma unroll
    for (int c = 0; c < 3; ++c)
        acc[c] = __reduce_add_sync(0xFFFFFFFFu, acc[c]);
    if (lane == 0) {
        s_wred[warp][0] = acc[0];
        s_wred[warp][1] = acc[1];
        s_wred[warp][2] = acc[2];
    }
    __syncthreads();

    if (warp == 0) {
        unsigned int t0 = s_wred[lane][0];
        unsigned int t1 = s_wred[lane][1];
        unsigned int t2 = s_wred[lane][2];
        t0 = __reduce_add_sync(0xFFFFFFFFu, t0);
        t1 = __reduce_add_sync(0xFFFFFFFFu, t1);
        t2 = __reduce_add_sync(0xFFFFFFFFu, t2);
        if (lane == 0)
            *out = sqrtf((float)t0) + sqrtf((float)t1) + sqrtf((float)t2);
    }
}

extern "C" void kernel_launch(void* const* d_in, const int* in_sizes, int n_in,
                              void* d_out, int out_size)
{
    const float* target = (const float*)d_in[0];  // (3, 256, 1) fp32
    const float* output = (const float*)d_in[1];  // (3, 256, 1) fp32
    float* out = (float*)d_out;                   // scalar fp32
    (void)in_sizes; (void)n_in; (void)out_size;

    l2hist_kernel<<<1, TPB>>>(target, output, out);
}